// round 8
// baseline (speedup 1.0000x reference)
#include <cuda_runtime.h>
#include <cstdint>

// Problem-instance constants (fixed by setup_inputs)
#define N_ENT   200000
#define N_REL   500
#define BATCH   64
#define NWORDS  16                 // 512 bits >= 500 relations
#define MASKW   (N_ENT / 32)       // 6250 mask words per query
#define MAXK    16
#define CAND    256                // candidates per main CTA
#define NCHUNKS ((N_ENT + CAND - 1) / CAND)   // 782
#define CSTRIDE 257                // padded smem stride
#define FCAP    4096               // final survivor buffer (= full rescan size)

// ---------------- device scratch (no allocations allowed) ----------------
__device__ uint32_t g_qw[BATCH * NWORDS];            // query bitmaps
__device__ float    g_sq[BATCH];                     // s_q
__device__ uint32_t g_mask[(size_t)BATCH * MASKW];   // keep bits
__device__ uint32_t g_cmax[(size_t)BATCH * NCHUNKS]; // chunk-max ord (u32)

// ord = keep ? bits|0x80000000 : 0   (vals >= 0, so this is order-preserving)
__device__ __forceinline__ uint32_t u32max_(uint32_t a, uint32_t b) {
    return a > b ? a : b;
}

// Pack one row's chunk c (128 elems) into 4 words via nibble+butterfly.
__device__ __forceinline__ uint32_t pack_chunk(const float* __restrict__ row,
                                               int c, int lane, bool rowValid,
                                               float* s0out) {
    const int e = c * 128 + lane * 4;
    float4 f = make_float4(0.f, 0.f, 0.f, 0.f);
    if (rowValid && e + 3 < N_REL)
        f = *(const float4*)(row + e);
    if (c == 0 && lane == 0) *s0out = f.x;     // ev[r,0]
    uint32_t nib = (f.x != 0.0f ? 1u : 0u) | (f.y != 0.0f ? 2u : 0u)
                 | (f.z != 0.0f ? 4u : 0u) | (f.w != 0.0f ? 8u : 0u);
    uint32_t v = nib;
    #pragma unroll
    for (int s = 0; s < 3; ++s) {
        const int step = 1 << s;
        const int w = 4 << s;
        uint32_t other = __shfl_xor_sync(0xffffffffu, v, step);
        v = (lane & step) ? ((v << w) | other) : (v | (other << w));
    }
    return v;
}

// ============================================================================
// 0) qpack: 64 CTAs x 128 threads; warp c packs chunk c of the query row.
// ============================================================================
__global__ void __launch_bounds__(128)
qpack_kernel(const float* __restrict__ ev, const int* __restrict__ qent) {
    const int b    = blockIdx.x;
    const int warp = threadIdx.x >> 5;
    const int lane = threadIdx.x & 31;
    const float* row = ev + (size_t)qent[b] * N_REL;
    float s0 = 0.0f;
    uint32_t v = pack_chunk(row, warp, lane, true, &s0);
    if ((lane & 7) == 0) g_qw[b * NWORDS + 4 * warp + (lane >> 3)] = v;
    if (warp == 0 && lane == 0) g_sq[b] = s0;
}

// ============================================================================
// 1) main: candidate-pack + popcount sim + per-chunk max-ord selection
// ============================================================================
__global__ void __launch_bounds__(256)
main_kernel(const float* __restrict__ ev, const int* __restrict__ qrel,
            float* __restrict__ out) {
    __shared__ uint32_t cws[NWORDS * CSTRIDE];   // candidate bitmaps (transposed)
    __shared__ float    snm[CAND];
    __shared__ uint32_t qsm[BATCH * NWORDS];
    __shared__ float    sqm[BATCH];
    __shared__ int      relwS[BATCH];
    __shared__ uint32_t relshS[BATCH];
    __shared__ uint32_t wkey[BATCH * 8];         // per-warp max ord

    const int tid  = threadIdx.x;
    const int warp = tid >> 5;
    const int lane = tid & 31;

    // stage query data (g_qw/g_sq from qpack; 4 KB exact)
    ((uint4*)qsm)[tid] = ((const uint4*)g_qw)[tid];
    if (tid < BATCH) {
        sqm[tid] = g_sq[tid];
        int rr = qrel[tid];
        relwS[tid]  = rr >> 5;
        relshS[tid] = (uint32_t)(rr & 31);
    }

    // ---- phase A: pack 32 candidate rows per warp ----
    const int row0 = blockIdx.x * CAND + warp * 32;
    #pragma unroll 2
    for (int j = 0; j < 32; ++j) {
        const int r = row0 + j;
        const bool rv = (r < N_ENT);
        const float* row = ev + (size_t)r * N_REL;
        float s0 = 0.0f;
        #pragma unroll
        for (int c = 0; c < 4; ++c) {
            uint32_t v = pack_chunk(row, c, lane, rv, &s0);
            if ((lane & 7) == 0)
                cws[(4 * c + (lane >> 3)) * CSTRIDE + warp * 32 + j] = v;
        }
        if (lane == 0) snm[warp * 32 + j] = s0;
    }
    __syncthreads();

    // ---- phase B: 64-query popcount + selection ----
    const int n = blockIdx.x * CAND + tid;
    const bool valid = (n < N_ENT);
    uint32_t cw[NWORDS];
    #pragma unroll
    for (int w = 0; w < NWORDS; ++w) cw[w] = cws[w * CSTRIDE + tid];
    const float sn = snm[tid];
    const int wordIdx = n >> 5;     // warp-uniform

    #pragma unroll 4
    for (int b = 0; b < BATCH; ++b) {
        const uint4* q4 = (const uint4*)(qsm + b * NWORDS);
        int cnt = 0;
        #pragma unroll
        for (int g = 0; g < 4; ++g) {
            uint4 q = q4[g];
            cnt += __popc(cw[g*4+0] & q.x) + __popc(cw[g*4+1] & q.y)
                 + __popc(cw[g*4+2] & q.z) + __popc(cw[g*4+3] & q.w);
        }
        float val = __fmul_rn(__fmul_rn((float)cnt, sn), sqm[b]);
        uint32_t kw = cws[relwS[b] * CSTRIDE + tid];
        uint32_t kb = (kw >> relshS[b]) & 1u;        // invalid rows: words are 0
        uint32_t bal = __ballot_sync(0xffffffffu, kb);

        // branchless ord; per-warp max (index recovered later by rescan)
        uint32_t ord  = (__float_as_uint(val) | 0x80000000u) & (0u - kb);
        uint32_t wmax = __reduce_max_sync(0xffffffffu, ord);
        if (lane == 0) wkey[b * 8 + warp] = wmax;

        if (valid) {
            out[(size_t)b * N_ENT + n] = val;                 // coalesced
            if (lane == 0) g_mask[(size_t)b * MASKW + wordIdx] = bal;
        }
    }
    __syncthreads();

    if (tid < BATCH) {
        uint32_t m = wkey[tid * 8];
        #pragma unroll
        for (int w = 1; w < 8; ++w) m = u32max_(m, wkey[tid * 8 + w]);
        g_cmax[(size_t)tid * NCHUNKS + blockIdx.x] = m;
    }
}

// ============================================================================
// 2) final: per query (64 CTAs): rank chunks by (maxord, smaller-id-first);
//    rescan the 16 surviving chunks (4K sims, L2-hot); compact ord >= tau;
//    exact rank-select on full (ord, ~idx) keys; write output.
// ============================================================================
__global__ void __launch_bounds__(512)
final_kernel(const float* __restrict__ sim, const int* __restrict__ kptr,
             float* __restrict__ out) {
    __shared__ uint32_t ck[NCHUNKS];
    __shared__ unsigned long long sbuf[FCAP];
    __shared__ unsigned long long spart[MAXK];
    __shared__ uint32_t stau;
    __shared__ int chunkIds[MAXK];
    __shared__ int scnt;

    const int b   = blockIdx.x;
    const int tid = threadIdx.x;

    for (int i = tid; i < NCHUNKS; i += 512)
        ck[i] = g_cmax[(size_t)b * NCHUNKS + i];
    if (tid == 0) scnt = 0;
    __syncthreads();

    // rank chunks by key = (maxord << 32) | ~id  (unique)
    for (int i = tid; i < NCHUNKS; i += 512) {
        unsigned long long key = ((unsigned long long)ck[i] << 32) | (uint32_t)(~i);
        int rank = 0;
        for (int j = 0; j < NCHUNKS; ++j) {
            unsigned long long kj = ((unsigned long long)ck[j] << 32) | (uint32_t)(~j);
            rank += (kj > key);
        }
        if (rank == MAXK - 1) stau = ck[i];
        if (rank < MAXK) chunkIds[rank] = i;
    }
    __syncthreads();
    const uint32_t tau = stau;

    // rescan the 16 surviving chunks; compact elements with ord >= tau
    const float*    row  = sim + (size_t)b * N_ENT;
    const uint32_t* mrow = g_mask + (size_t)b * MASKW;
    for (int e = tid; e < MAXK * CAND; e += 512) {
        int c = chunkIds[e >> 8];
        int n = c * CAND + (e & 255);
        if (n < N_ENT) {
            float x = row[n];
            uint32_t kb = (mrow[n >> 5] >> (n & 31)) & 1u;
            uint32_t ord = (__float_as_uint(x) | 0x80000000u) & (0u - kb);
            if (ord >= tau) {
                int p = atomicAdd(&scnt, 1);
                sbuf[p] = ((unsigned long long)ord << 32) | (uint32_t)(~n);
            }
        }
    }
    __syncthreads();
    const int cnt = scnt;    // >= 16 guaranteed (each selected chunk's max >= tau)

    for (int i = tid; i < cnt; i += 512) {
        unsigned long long key = sbuf[i];
        int rank = 0;
        for (int j = 0; j < cnt; ++j) rank += (sbuf[j] > key);
        if (rank < MAXK) spart[rank] = key;
    }
    __syncthreads();

    if (tid == 0) {
        int kk = kptr[0] + 5;                 // k + K_EXTRA
        if (kk > MAXK) kk = MAXK;
        const float NEG_INF = __int_as_float(0xFF800000);
        size_t obase = (size_t)BATCH * N_ENT;
        float* out_v = out + obase + (size_t)b * kk;
        float* out_i = out + obase + (size_t)BATCH * kk + (size_t)b * kk;
        for (int j = 0; j < kk; ++j) {
            unsigned long long key = spart[j];
            uint32_t hi = (uint32_t)(key >> 32);
            out_v[j] = (hi & 0x80000000u) ? __uint_as_float(hi ^ 0x80000000u)
                                          : NEG_INF;
            out_i[j] = (float)(int)(~(uint32_t)key);
        }
    }
}

// ============================================================================
extern "C" void kernel_launch(void* const* d_in, const int* in_sizes, int n_in,
                              void* d_out, int out_size) {
    const float* ev   = (const float*)d_in[0];
    const int*   qe   = (const int*)d_in[1];
    const int*   qr   = (const int*)d_in[2];
    const int*   kptr = (const int*)d_in[3];
    float* out = (float*)d_out;

    qpack_kernel<<<BATCH, 128>>>(ev, qe);                // 64 CTAs
    main_kernel<<<NCHUNKS, 256>>>(ev, qr, out);          // 782 CTAs
    final_kernel<<<BATCH, 512>>>(out, kptr, out);        // 64 CTAs
}

// round 9
// speedup vs baseline: 1.0652x; 1.0652x over previous
#include <cuda_runtime.h>
#include <cstdint>

// Problem-instance constants (fixed by setup_inputs)
#define N_ENT   200000
#define N_REL   500
#define BATCH   64
#define NWORDS  16                 // 512 bits >= 500 relations
#define MASKW   (N_ENT / 32)       // 6250 mask words per query
#define MAXK    16
#define CAND    256                // candidates per main CTA
#define NCHUNKS ((N_ENT + CAND - 1) / CAND)   // 782
#define CSTRIDE 257                // padded smem stride
#define FCAP    4096               // final survivor buffer (= full rescan size)

// ---------------- device scratch (no allocations allowed) ----------------
__device__ uint32_t g_qw[BATCH * NWORDS];            // query bitmaps
__device__ float    g_sq[BATCH];                     // s_q
__device__ uint32_t g_mask[(size_t)BATCH * MASKW];   // keep bits
__device__ uint32_t g_cmax[(size_t)BATCH * NCHUNKS]; // chunk-max ord (u32)

// ord = keep ? bits|0x80000000 : 0   (vals >= 0, so this is order-preserving)
__device__ __forceinline__ uint32_t u32max_(uint32_t a, uint32_t b) {
    return a > b ? a : b;
}

// Pack one row's chunk c (128 elems) into 4 words via nibble+butterfly.
__device__ __forceinline__ uint32_t pack_chunk(const float* __restrict__ row,
                                               int c, int lane, bool rowValid,
                                               float* s0out) {
    const int e = c * 128 + lane * 4;
    float4 f = make_float4(0.f, 0.f, 0.f, 0.f);
    if (rowValid && e + 3 < N_REL)
        f = *(const float4*)(row + e);
    if (c == 0 && lane == 0) *s0out = f.x;     // ev[r,0]
    uint32_t nib = (f.x != 0.0f ? 1u : 0u) | (f.y != 0.0f ? 2u : 0u)
                 | (f.z != 0.0f ? 4u : 0u) | (f.w != 0.0f ? 8u : 0u);
    uint32_t v = nib;
    #pragma unroll
    for (int s = 0; s < 3; ++s) {
        const int step = 1 << s;
        const int w = 4 << s;
        uint32_t other = __shfl_xor_sync(0xffffffffu, v, step);
        v = (lane & step) ? ((v << w) | other) : (v | (other << w));
    }
    return v;
}

// ============================================================================
// 0) qpack: 64 CTAs x 128 threads; warp c packs chunk c of the query row.
// ============================================================================
__global__ void __launch_bounds__(128)
qpack_kernel(const float* __restrict__ ev, const int* __restrict__ qent) {
    const int b    = blockIdx.x;
    const int warp = threadIdx.x >> 5;
    const int lane = threadIdx.x & 31;
    const float* row = ev + (size_t)qent[b] * N_REL;
    float s0 = 0.0f;
    uint32_t v = pack_chunk(row, warp, lane, true, &s0);
    if ((lane & 7) == 0) g_qw[b * NWORDS + 4 * warp + (lane >> 3)] = v;
    if (warp == 0 && lane == 0) g_sq[b] = s0;
}

// ============================================================================
// 1) main: candidate-pack + popcount sim + per-chunk max-ord selection
//    Config: 3 CTAs/SM (measured best, R7) + phase-A unroll 4 + cheap u32
//    selection (measured best, R8).
// ============================================================================
__global__ void __launch_bounds__(256, 3)
main_kernel(const float* __restrict__ ev, const int* __restrict__ qrel,
            float* __restrict__ out) {
    __shared__ uint32_t cws[NWORDS * CSTRIDE];   // candidate bitmaps (transposed)
    __shared__ float    snm[CAND];
    __shared__ uint32_t qsm[BATCH * NWORDS];
    __shared__ float    sqm[BATCH];
    __shared__ int      relwS[BATCH];
    __shared__ uint32_t relshS[BATCH];
    __shared__ uint32_t wkey[BATCH * 8];         // per-warp max ord

    const int tid  = threadIdx.x;
    const int warp = tid >> 5;
    const int lane = tid & 31;

    // stage query data (g_qw/g_sq from qpack; 4 KB exact)
    ((uint4*)qsm)[tid] = ((const uint4*)g_qw)[tid];
    if (tid < BATCH) {
        sqm[tid] = g_sq[tid];
        int rr = qrel[tid];
        relwS[tid]  = rr >> 5;
        relshS[tid] = (uint32_t)(rr & 31);
    }

    // ---- phase A: pack 32 candidate rows per warp ----
    const int row0 = blockIdx.x * CAND + warp * 32;
    #pragma unroll 4
    for (int j = 0; j < 32; ++j) {
        const int r = row0 + j;
        const bool rv = (r < N_ENT);
        const float* row = ev + (size_t)r * N_REL;
        float s0 = 0.0f;
        #pragma unroll
        for (int c = 0; c < 4; ++c) {
            uint32_t v = pack_chunk(row, c, lane, rv, &s0);
            if ((lane & 7) == 0)
                cws[(4 * c + (lane >> 3)) * CSTRIDE + warp * 32 + j] = v;
        }
        if (lane == 0) snm[warp * 32 + j] = s0;
    }
    __syncthreads();

    // ---- phase B: 64-query popcount + selection ----
    const int n = blockIdx.x * CAND + tid;
    const bool valid = (n < N_ENT);
    uint32_t cw[NWORDS];
    #pragma unroll
    for (int w = 0; w < NWORDS; ++w) cw[w] = cws[w * CSTRIDE + tid];
    const float sn = snm[tid];
    const int wordIdx = n >> 5;     // warp-uniform

    #pragma unroll 4
    for (int b = 0; b < BATCH; ++b) {
        const uint4* q4 = (const uint4*)(qsm + b * NWORDS);
        int cnt = 0;
        #pragma unroll
        for (int g = 0; g < 4; ++g) {
            uint4 q = q4[g];
            cnt += __popc(cw[g*4+0] & q.x) + __popc(cw[g*4+1] & q.y)
                 + __popc(cw[g*4+2] & q.z) + __popc(cw[g*4+3] & q.w);
        }
        float val = __fmul_rn(__fmul_rn((float)cnt, sn), sqm[b]);
        uint32_t kw = cws[relwS[b] * CSTRIDE + tid];
        uint32_t kb = (kw >> relshS[b]) & 1u;        // invalid rows: words are 0
        uint32_t bal = __ballot_sync(0xffffffffu, kb);

        // branchless ord; per-warp max (index recovered later by rescan)
        uint32_t ord  = (__float_as_uint(val) | 0x80000000u) & (0u - kb);
        uint32_t wmax = __reduce_max_sync(0xffffffffu, ord);
        if (lane == 0) wkey[b * 8 + warp] = wmax;

        if (valid) {
            out[(size_t)b * N_ENT + n] = val;                 // coalesced
            if (lane == 0) g_mask[(size_t)b * MASKW + wordIdx] = bal;
        }
    }
    __syncthreads();

    if (tid < BATCH) {
        uint32_t m = wkey[tid * 8];
        #pragma unroll
        for (int w = 1; w < 8; ++w) m = u32max_(m, wkey[tid * 8 + w]);
        g_cmax[(size_t)tid * NCHUNKS + blockIdx.x] = m;
    }
}

// ============================================================================
// 2) final: per query (64 CTAs): rank chunks by (maxord, smaller-id-first);
//    rescan the 16 surviving chunks (4K sims, L2-hot); compact ord >= tau;
//    exact rank-select on full (ord, ~idx) keys; write output.
// ============================================================================
__global__ void __launch_bounds__(512)
final_kernel(const float* __restrict__ sim, const int* __restrict__ kptr,
             float* __restrict__ out) {
    __shared__ uint32_t ck[NCHUNKS];
    __shared__ unsigned long long sbuf[FCAP];
    __shared__ unsigned long long spart[MAXK];
    __shared__ uint32_t stau;
    __shared__ int chunkIds[MAXK];
    __shared__ int scnt;

    const int b   = blockIdx.x;
    const int tid = threadIdx.x;

    for (int i = tid; i < NCHUNKS; i += 512)
        ck[i] = g_cmax[(size_t)b * NCHUNKS + i];
    if (tid == 0) scnt = 0;
    __syncthreads();

    // rank chunks by key = (maxord << 32) | ~id  (unique)
    for (int i = tid; i < NCHUNKS; i += 512) {
        unsigned long long key = ((unsigned long long)ck[i] << 32) | (uint32_t)(~i);
        int rank = 0;
        for (int j = 0; j < NCHUNKS; ++j) {
            unsigned long long kj = ((unsigned long long)ck[j] << 32) | (uint32_t)(~j);
            rank += (kj > key);
        }
        if (rank == MAXK - 1) stau = ck[i];
        if (rank < MAXK) chunkIds[rank] = i;
    }
    __syncthreads();
    const uint32_t tau = stau;

    // rescan the 16 surviving chunks; compact elements with ord >= tau
    const float*    row  = sim + (size_t)b * N_ENT;
    const uint32_t* mrow = g_mask + (size_t)b * MASKW;
    for (int e = tid; e < MAXK * CAND; e += 512) {
        int c = chunkIds[e >> 8];
        int n = c * CAND + (e & 255);
        if (n < N_ENT) {
            float x = row[n];
            uint32_t kb = (mrow[n >> 5] >> (n & 31)) & 1u;
            uint32_t ord = (__float_as_uint(x) | 0x80000000u) & (0u - kb);
            if (ord >= tau) {
                int p = atomicAdd(&scnt, 1);
                sbuf[p] = ((unsigned long long)ord << 32) | (uint32_t)(~n);
            }
        }
    }
    __syncthreads();
    const int cnt = scnt;    // >= 16 guaranteed (each selected chunk's max >= tau)

    for (int i = tid; i < cnt; i += 512) {
        unsigned long long key = sbuf[i];
        int rank = 0;
        for (int j = 0; j < cnt; ++j) rank += (sbuf[j] > key);
        if (rank < MAXK) spart[rank] = key;
    }
    __syncthreads();

    if (tid == 0) {
        int kk = kptr[0] + 5;                 // k + K_EXTRA
        if (kk > MAXK) kk = MAXK;
        const float NEG_INF = __int_as_float(0xFF800000);
        size_t obase = (size_t)BATCH * N_ENT;
        float* out_v = out + obase + (size_t)b * kk;
        float* out_i = out + obase + (size_t)BATCH * kk + (size_t)b * kk;
        for (int j = 0; j < kk; ++j) {
            unsigned long long key = spart[j];
            uint32_t hi = (uint32_t)(key >> 32);
            out_v[j] = (hi & 0x80000000u) ? __uint_as_float(hi ^ 0x80000000u)
                                          : NEG_INF;
            out_i[j] = (float)(int)(~(uint32_t)key);
        }
    }
}

// ============================================================================
extern "C" void kernel_launch(void* const* d_in, const int* in_sizes, int n_in,
                              void* d_out, int out_size) {
    const float* ev   = (const float*)d_in[0];
    const int*   qe   = (const int*)d_in[1];
    const int*   qr   = (const int*)d_in[2];
    const int*   kptr = (const int*)d_in[3];
    float* out = (float*)d_out;

    qpack_kernel<<<BATCH, 128>>>(ev, qe);                // 64 CTAs
    main_kernel<<<NCHUNKS, 256>>>(ev, qr, out);          // 782 CTAs
    final_kernel<<<BATCH, 512>>>(out, kptr, out);        // 64 CTAs
}